// round 2
// baseline (speedup 1.0000x reference)
#include <cuda_runtime.h>
#include <cuda_bf16.h>
#include <cstdint>

// Problem constants
#define NB 2048
#define NQ 128
#define NS 128   // K
#define NH 32    // N (hidden)
#define NC (NQ * NS)

// smem strides (bf16 elems). 136 = 128 + 8 pad -> 272B rows, conflict-free for
// ldmatrix (16B phases cover all banks) and for B-fragment LDS.32.
#define XSTRIDE 136
#define WSTRIDE 136

// ---- SMEM byte layout ----
#define OFF_W2   0                       // 32 f32
#define OFF_B1   128                     // 32 f32
#define OFF_WHI  256                     // 32*136*2 = 8704
#define OFF_WLO  (OFF_WHI + 8704)        // 8960
#define OFF_XHI  (OFF_WLO + 8704)        // 17664 : 128*136*2 = 34816
#define OFF_XLO  (OFF_XHI + 34816)       // 52480
#define SMEM_TOTAL (OFF_XLO + 34816)     // 87296

__device__ __forceinline__ uint32_t smem_u32(const void* p) {
    uint32_t a;
    asm("{ .reg .u64 t; cvta.to.shared.u64 t, %1; cvt.u32.u64 %0, t; }" : "=r"(a) : "l"(p));
    return a;
}

__device__ __forceinline__ void ldm_x4(uint32_t* r, uint32_t addr) {
    asm volatile("ldmatrix.sync.aligned.m8n8.x4.shared.b16 {%0,%1,%2,%3}, [%4];"
                 : "=r"(r[0]), "=r"(r[1]), "=r"(r[2]), "=r"(r[3]) : "r"(addr));
}

__device__ __forceinline__ void mma16816(float* d, const uint32_t* a, uint32_t b0, uint32_t b1) {
    asm volatile(
        "mma.sync.aligned.m16n8k16.row.col.f32.bf16.bf16.f32 "
        "{%0,%1,%2,%3}, {%4,%5,%6,%7}, {%8,%9}, {%0,%1,%2,%3};"
        : "+f"(d[0]), "+f"(d[1]), "+f"(d[2]), "+f"(d[3])
        : "r"(a[0]), "r"(a[1]), "r"(a[2]), "r"(a[3]), "r"(b0), "r"(b1));
}

__global__ void __launch_bounds__(128)
div_enc_kernel(const float* __restrict__ x, const float* __restrict__ W1,
               const float* __restrict__ b1, const float* __restrict__ W2,
               const float* __restrict__ b2, float* __restrict__ out) {
    extern __shared__ char smem[];
    const uint32_t sbase = smem_u32(smem);
    const int tid  = threadIdx.x;
    const int wid  = tid >> 5;
    const int lane = tid & 31;

    const int q     = blockIdx.x & (NQ - 1);
    const int btile = blockIdx.x >> 7;

    // ---- stage W2 / b1 ----
    if (tid < 32) {
        ((float*)(smem + OFF_W2))[tid] = W2[q * NH + tid];
        ((float*)(smem + OFF_B1))[tid] = b1[q * NH + tid];
    }

    // ---- W1[q] (gmem [s][h]) -> smem Bt[h][s] K-major, split hi/lo ----
    {
        const float* w1q = W1 + (size_t)q * NS * NH;
        const int h  = tid & 31;
        const int sb = tid >> 5;
        __nv_bfloat16* whi = (__nv_bfloat16*)(smem + OFF_WHI);
        __nv_bfloat16* wlo = (__nv_bfloat16*)(smem + OFF_WLO);
#pragma unroll 8
        for (int j = 0; j < 32; j++) {
            const int s = j * 4 + sb;
            float v = w1q[s * NH + h];               // coalesced: h contiguous
            __nv_bfloat16 hi = __float2bfloat16(v);
            __nv_bfloat16 lo = __float2bfloat16(v - __bfloat162float(hi));
            whi[h * WSTRIDE + s] = hi;
            wlo[h * WSTRIDE + s] = lo;
        }
    }

    // ---- x tile (128 rows x 128 k) -> smem row-major, split hi/lo ----
    {
        const float* xb = x + (size_t)(btile * 128) * NC + (size_t)q * NS;
        const int k = lane * 4;
#pragma unroll 8
        for (int j = 0; j < 32; j++) {
            const int r = j * 4 + wid;
            const float4 v = *(const float4*)(xb + (size_t)r * NC + k);
            __nv_bfloat16 h0 = __float2bfloat16(v.x);
            __nv_bfloat16 h1 = __float2bfloat16(v.y);
            __nv_bfloat16 h2 = __float2bfloat16(v.z);
            __nv_bfloat16 h3 = __float2bfloat16(v.w);
            __nv_bfloat16 l0 = __float2bfloat16(v.x - __bfloat162float(h0));
            __nv_bfloat16 l1 = __float2bfloat16(v.y - __bfloat162float(h1));
            __nv_bfloat16 l2 = __float2bfloat16(v.z - __bfloat162float(h2));
            __nv_bfloat16 l3 = __float2bfloat16(v.w - __bfloat162float(h3));
            uint2 hp, lp;
            hp.x = (uint32_t)__bfloat16_as_ushort(h0) | ((uint32_t)__bfloat16_as_ushort(h1) << 16);
            hp.y = (uint32_t)__bfloat16_as_ushort(h2) | ((uint32_t)__bfloat16_as_ushort(h3) << 16);
            lp.x = (uint32_t)__bfloat16_as_ushort(l0) | ((uint32_t)__bfloat16_as_ushort(l1) << 16);
            lp.y = (uint32_t)__bfloat16_as_ushort(l2) | ((uint32_t)__bfloat16_as_ushort(l3) << 16);
            const uint32_t boff = (uint32_t)(r * XSTRIDE + k) * 2u;
            *(uint2*)(smem + OFF_XHI + boff) = hp;
            *(uint2*)(smem + OFF_XLO + boff) = lp;
        }
    }

    __syncthreads();

    // ---- mainloop: warp computes rows [wid*32, wid*32+32) x 32 h, K=128 ----
    float acc[2][4][4];
#pragma unroll
    for (int mt = 0; mt < 2; mt++)
#pragma unroll
        for (int nt = 0; nt < 4; nt++)
#pragma unroll
            for (int i = 0; i < 4; i++) acc[mt][nt][i] = 0.f;

    // ldmatrix address: rows m_base + (lane&15), k-half (lane>>4)*8
    const uint32_t arow = (uint32_t)((wid * 32 + (lane & 15)) * XSTRIDE) * 2u
                        + (uint32_t)((lane >> 4) * 16);
    const uint32_t aHiBase = sbase + OFF_XHI + arow;
    const uint32_t aLoBase = sbase + OFF_XLO + arow;
    const uint32_t MT_STEP = (uint32_t)(16 * XSTRIDE) * 2u;

    const char* bHiBase = smem + OFF_WHI + ((lane >> 2) * WSTRIDE + (lane & 3) * 2) * 2;
    const char* bLoBase = smem + OFF_WLO + ((lane >> 2) * WSTRIDE + (lane & 3) * 2) * 2;

#pragma unroll
    for (int ks = 0; ks < 8; ks++) {
        const uint32_t kb = (uint32_t)ks * 32u;   // 16 elems * 2B
        uint32_t aHi0[4], aHi1[4], aLo0[4], aLo1[4];
        ldm_x4(aHi0, aHiBase + kb);
        ldm_x4(aHi1, aHiBase + MT_STEP + kb);
        ldm_x4(aLo0, aLoBase + kb);
        ldm_x4(aLo1, aLoBase + MT_STEP + kb);
#pragma unroll
        for (int nt = 0; nt < 4; nt++) {
            const uint32_t noff = (uint32_t)(nt * 8 * WSTRIDE) * 2u + kb;
            const uint32_t bh0 = *(const uint32_t*)(bHiBase + noff);
            const uint32_t bh1 = *(const uint32_t*)(bHiBase + noff + 16);
            const uint32_t bl0 = *(const uint32_t*)(bLoBase + noff);
            const uint32_t bl1 = *(const uint32_t*)(bLoBase + noff + 16);
            mma16816(acc[0][nt], aHi0, bh0, bh1);
            mma16816(acc[1][nt], aHi1, bh0, bh1);
            mma16816(acc[0][nt], aHi0, bl0, bl1);
            mma16816(acc[1][nt], aHi1, bl0, bl1);
            mma16816(acc[0][nt], aLo0, bh0, bh1);
            mma16816(acc[1][nt], aLo1, bh0, bh1);
        }
    }

    // ---- epilogue: +b1, ELU, dot W2, quad-reduce, store ----
    float b1v[4][2], w2v[4][2];
    const float* s_b1 = (const float*)(smem + OFF_B1);
    const float* s_w2 = (const float*)(smem + OFF_W2);
#pragma unroll
    for (int nt = 0; nt < 4; nt++)
#pragma unroll
        for (int i = 0; i < 2; i++) {
            const int h = nt * 8 + (lane & 3) * 2 + i;
            b1v[nt][i] = s_b1[h];
            w2v[nt][i] = s_w2[h];
        }
    const float b2q = b2[q];

#pragma unroll
    for (int mt = 0; mt < 2; mt++) {
        float p0 = 0.f, p1 = 0.f;
#pragma unroll
        for (int nt = 0; nt < 4; nt++) {
#pragma unroll
            for (int i = 0; i < 2; i++) {
                float hv = acc[mt][nt][i] + b1v[nt][i];
                float e  = (hv > 0.f) ? hv : (__expf(hv) - 1.0f);
                p0 = fmaf(e, w2v[nt][i], p0);
                hv = acc[mt][nt][2 + i] + b1v[nt][i];
                e  = (hv > 0.f) ? hv : (__expf(hv) - 1.0f);
                p1 = fmaf(e, w2v[nt][i], p1);
            }
        }
        p0 += __shfl_xor_sync(0xFFFFFFFFu, p0, 1);
        p0 += __shfl_xor_sync(0xFFFFFFFFu, p0, 2);
        p1 += __shfl_xor_sync(0xFFFFFFFFu, p1, 1);
        p1 += __shfl_xor_sync(0xFFFFFFFFu, p1, 2);
        if ((lane & 3) == 0) {
            const int m = btile * 128 + wid * 32 + mt * 16 + (lane >> 2);
            out[(size_t)m * NQ + q]       = p0 + b2q;
            out[(size_t)(m + 8) * NQ + q] = p1 + b2q;
        }
    }
}

extern "C" void kernel_launch(void* const* d_in, const int* in_sizes, int n_in,
                              void* d_out, int out_size) {
    const float* x  = (const float*)d_in[0];
    const float* W1 = (const float*)d_in[1];
    const float* b1 = (const float*)d_in[2];
    const float* W2 = (const float*)d_in[3];
    const float* b2 = (const float*)d_in[4];
    float* out = (float*)d_out;

    cudaFuncSetAttribute(div_enc_kernel, cudaFuncAttributeMaxDynamicSharedMemorySize, SMEM_TOTAL);
    div_enc_kernel<<<(NB / 128) * NQ, 128, SMEM_TOTAL>>>(x, W1, b1, W2, b2, out);
}

// round 4
// speedup vs baseline: 1.5342x; 1.5342x over previous
#include <cuda_runtime.h>
#include <cuda_bf16.h>
#include <cstdint>

// Problem constants
#define NB 2048
#define NQ 128
#define NS 128   // K
#define NH 32    // N (hidden)
#define NC (NQ * NS)

// W smem stride in bf16 elems: 136 -> 272B rows; B-fragment LDS.32 reads are
// conflict-free ((lane>>2)*68 + (lane&3) words covers 32 distinct banks).
#define WSTRIDE 136

// ---- SMEM byte layout (W only; x goes gmem->registers) ----
#define OFF_W2   0                       // 32 f32
#define OFF_B1   128                     // 32 f32
#define OFF_WHI  256                     // 32*136*2 = 8704
#define OFF_WLO  (OFF_WHI + 8704)        // 8960
#define SMEM_TOTAL (OFF_WLO + 8704)      // 17664

__device__ __forceinline__ void mma16816(float* d, const uint32_t* a, uint32_t b0, uint32_t b1) {
    asm volatile(
        "mma.sync.aligned.m16n8k16.row.col.f32.bf16.bf16.f32 "
        "{%0,%1,%2,%3}, {%4,%5,%6,%7}, {%8,%9}, {%0,%1,%2,%3};"
        : "+f"(d[0]), "+f"(d[1]), "+f"(d[2]), "+f"(d[3])
        : "r"(a[0]), "r"(a[1]), "r"(a[2]), "r"(a[3]), "r"(b0), "r"(b1));
}

// fp32x2 -> (bf16x2 hi, bf16x2 lo) two-term split, packed for mma operands.
__device__ __forceinline__ void cvt_split(float2 v, uint32_t& hi, uint32_t& lo) {
    __nv_bfloat162 h2 = __float22bfloat162_rn(v);
    float2 hf = __bfloat1622float2(h2);
    float2 l;
    l.x = v.x - hf.x;
    l.y = v.y - hf.y;
    __nv_bfloat162 l2 = __float22bfloat162_rn(l);
    hi = *reinterpret_cast<uint32_t*>(&h2);
    lo = *reinterpret_cast<uint32_t*>(&l2);
}

__global__ void __launch_bounds__(128, 6)
div_enc_kernel(const float* __restrict__ x, const float* __restrict__ W1,
               const float* __restrict__ b1, const float* __restrict__ W2,
               const float* __restrict__ b2, float* __restrict__ out) {
    extern __shared__ char smem[];
    const int tid  = threadIdx.x;
    const int wid  = tid >> 5;
    const int lane = tid & 31;

    const int q     = blockIdx.x & (NQ - 1);
    const int btile = blockIdx.x >> 7;

    // ---- stage W2 / b1 ----
    if (tid < 32) {
        ((float*)(smem + OFF_W2))[tid] = W2[q * NH + tid];
        ((float*)(smem + OFF_B1))[tid] = b1[q * NH + tid];
    }

    // ---- W1[q] (gmem [s][h]) -> smem Bt[h][s] K-major, split hi/lo ----
    {
        const float* w1q = W1 + (size_t)q * NS * NH;
        const int h  = tid & 31;
        const int sb = tid >> 5;
        __nv_bfloat16* whi = (__nv_bfloat16*)(smem + OFF_WHI);
        __nv_bfloat16* wlo = (__nv_bfloat16*)(smem + OFF_WLO);
#pragma unroll 8
        for (int j = 0; j < 32; j++) {
            const int s = j * 4 + sb;
            float v = w1q[s * NH + h];               // coalesced: h contiguous
            __nv_bfloat16 hi = __float2bfloat16(v);
            __nv_bfloat16 lo = __float2bfloat16(v - __bfloat162float(hi));
            whi[h * WSTRIDE + s] = hi;
            wlo[h * WSTRIDE + s] = lo;
        }
    }
    __syncthreads();

    // ---- mainloop: x straight from gmem into A fragments ----
    float acc[2][4][4];
#pragma unroll
    for (int mt = 0; mt < 2; mt++)
#pragma unroll
        for (int nt = 0; nt < 4; nt++)
#pragma unroll
            for (int i = 0; i < 4; i++) acc[mt][nt][i] = 0.f;

    // A-fragment base: row0 = btile*128 + wid*32 + (lane>>2), col pair (lane&3)*2
    const float* xb = x + (size_t)(btile * 128 + wid * 32 + (lane >> 2)) * NC
                        + (size_t)q * NS + (size_t)((lane & 3) * 2);

    const char* bHiBase = smem + OFF_WHI + ((lane >> 2) * WSTRIDE + (lane & 3) * 2) * 2;
    const char* bLoBase = smem + OFF_WLO + ((lane >> 2) * WSTRIDE + (lane & 3) * 2) * 2;

#pragma unroll
    for (int ks = 0; ks < 8; ks++) {
        // 16 independent LDG.64 per kstep (front-batched by the unroll)
        float2 v[2][2][2];   // [mt][rowhalf][colhalf]
#pragma unroll
        for (int mt = 0; mt < 2; mt++)
#pragma unroll
            for (int rh = 0; rh < 2; rh++)
#pragma unroll
                for (int ch = 0; ch < 2; ch++)
                    v[mt][rh][ch] = __ldcs((const float2*)(xb + mt * 16 * NC + rh * 8 * NC
                                                              + ks * 16 + ch * 8));

        uint32_t aHi[2][4], aLo[2][4];
#pragma unroll
        for (int mt = 0; mt < 2; mt++)
#pragma unroll
            for (int rh = 0; rh < 2; rh++)
#pragma unroll
                for (int ch = 0; ch < 2; ch++)
                    cvt_split(v[mt][rh][ch], aHi[mt][rh + 2 * ch], aLo[mt][rh + 2 * ch]);

        const uint32_t kb = (uint32_t)ks * 32u;   // 16 bf16 = 32 bytes
#pragma unroll
        for (int nt = 0; nt < 4; nt++) {
            const uint32_t noff = (uint32_t)(nt * 8 * WSTRIDE) * 2u + kb;
            const uint32_t bh0 = *(const uint32_t*)(bHiBase + noff);
            const uint32_t bh1 = *(const uint32_t*)(bHiBase + noff + 16);
            const uint32_t bl0 = *(const uint32_t*)(bLoBase + noff);
            const uint32_t bl1 = *(const uint32_t*)(bLoBase + noff + 16);
            mma16816(acc[0][nt], aHi[0], bh0, bh1);
            mma16816(acc[1][nt], aHi[1], bh0, bh1);
            mma16816(acc[0][nt], aHi[0], bl0, bl1);
            mma16816(acc[1][nt], aHi[1], bl0, bl1);
            mma16816(acc[0][nt], aLo[0], bh0, bh1);
            mma16816(acc[1][nt], aLo[1], bh0, bh1);
        }
    }

    // ---- epilogue: +b1, ELU, dot W2, quad-reduce, store ----
    float b1v[4][2], w2v[4][2];
    const float* s_b1 = (const float*)(smem + OFF_B1);
    const float* s_w2 = (const float*)(smem + OFF_W2);
#pragma unroll
    for (int nt = 0; nt < 4; nt++)
#pragma unroll
        for (int i = 0; i < 2; i++) {
            const int h = nt * 8 + (lane & 3) * 2 + i;
            b1v[nt][i] = s_b1[h];
            w2v[nt][i] = s_w2[h];
        }
    const float b2q = b2[q];

#pragma unroll
    for (int mt = 0; mt < 2; mt++) {
        float p0 = 0.f, p1 = 0.f;
#pragma unroll
        for (int nt = 0; nt < 4; nt++) {
#pragma unroll
            for (int i = 0; i < 2; i++) {
                float hv = acc[mt][nt][i] + b1v[nt][i];
                float e  = (hv > 0.f) ? hv : (__expf(hv) - 1.0f);
                p0 = fmaf(e, w2v[nt][i], p0);
                hv = acc[mt][nt][2 + i] + b1v[nt][i];
                e  = (hv > 0.f) ? hv : (__expf(hv) - 1.0f);
                p1 = fmaf(e, w2v[nt][i], p1);
            }
        }
        p0 += __shfl_xor_sync(0xFFFFFFFFu, p0, 1);
        p0 += __shfl_xor_sync(0xFFFFFFFFu, p0, 2);
        p1 += __shfl_xor_sync(0xFFFFFFFFu, p1, 1);
        p1 += __shfl_xor_sync(0xFFFFFFFFu, p1, 2);
        if ((lane & 3) == 0) {
            const int m = btile * 128 + wid * 32 + mt * 16 + (lane >> 2);
            out[(size_t)m * NQ + q]       = p0 + b2q;
            out[(size_t)(m + 8) * NQ + q] = p1 + b2q;
        }
    }
}

extern "C" void kernel_launch(void* const* d_in, const int* in_sizes, int n_in,
                              void* d_out, int out_size) {
    const float* x  = (const float*)d_in[0];
    const float* W1 = (const float*)d_in[1];
    const float* b1 = (const float*)d_in[2];
    const float* W2 = (const float*)d_in[3];
    const float* b2 = (const float*)d_in[4];
    float* out = (float*)d_out;

    cudaFuncSetAttribute(div_enc_kernel, cudaFuncAttributeMaxDynamicSharedMemorySize, SMEM_TOTAL);
    div_enc_kernel<<<(NB / 128) * NQ, 128, SMEM_TOTAL>>>(x, W1, b1, W2, b2, out);
}